// round 2
// baseline (speedup 1.0000x reference)
#include <cuda_runtime.h>
#include <cstdint>

#define N_NODES 100000
#define N_EDGES 1600000
#define HID 128
#define SA_STRIDE 132

// ---------------- scratch (device globals: no allocation allowed) -------------
__device__ float g_z[(size_t)N_NODES * HID];   // aggregated features
__device__ float g_h[(size_t)N_NODES * HID];   // layer output features
__device__ int   g_off[N_NODES + 1];           // CSR offsets (by dst)
__device__ int   g_cur[N_NODES];               // fill cursors
__device__ int   g_srcIdx[N_EDGES];            // CSR column (src node) indices
__device__ int   g_is64;                       // edge_index stored as int64?

// ---------------- dtype probe: int64 vs int32 edge_index ----------------------
__global__ void k_detect(const unsigned int* __restrict__ p) {
    __shared__ unsigned int sOr;
    if (threadIdx.x == 0) sOr = 0u;
    __syncthreads();
    unsigned int v = 0u;
    // If int64: words at odd positions (high halves) are all 0 (ids >= 0, < 2^31).
    for (int i = threadIdx.x; i < 4096; i += 256) v |= p[2 * i + 1];
    atomicOr(&sOr, v);
    __syncthreads();
    if (threadIdx.x == 0) g_is64 = (sOr == 0u) ? 1 : 0;
}

__device__ __forceinline__ int load_src(const int* ei, int e) {
    return g_is64 ? ei[2 * e] : ei[e];
}
__device__ __forceinline__ int load_dst(const int* ei, int e) {
    return g_is64 ? ei[2 * (N_EDGES + e)] : ei[N_EDGES + e];
}

// ---------------- CSR build ---------------------------------------------------
__global__ void k_zero() {
    int i = blockIdx.x * blockDim.x + threadIdx.x;
    if (i <= N_NODES) g_off[i] = 0;
}

__global__ void k_count(const int* __restrict__ ei) {
    int e = blockIdx.x * blockDim.x + threadIdx.x;
    if (e < N_EDGES) {
        int d = load_dst(ei, e);
        if ((unsigned)d < (unsigned)N_NODES) atomicAdd(&g_off[d + 1], 1);
    }
}

// single-block inclusive scan of g_off[0..N_NODES]; also writes g_cur
__global__ void k_scan() {
    __shared__ int ssum[1024];
    const int CH = 98;                      // 1024*98 = 100352 >= 100001
    int tid = threadIdx.x;
    int base = tid * CH;
    int s = 0;
    for (int i = 0; i < CH; i++) {
        int idx = base + i;
        if (idx <= N_NODES) s += g_off[idx];
    }
    ssum[tid] = s;
    __syncthreads();
    for (int st = 1; st < 1024; st <<= 1) {
        int v = (tid >= st) ? ssum[tid - st] : 0;
        __syncthreads();
        ssum[tid] += v;
        __syncthreads();
    }
    int run = (tid == 0) ? 0 : ssum[tid - 1];
    for (int i = 0; i < CH; i++) {
        int idx = base + i;
        if (idx <= N_NODES) {
            run += g_off[idx];
            g_off[idx] = run;               // start offset of node idx
            if (idx < N_NODES) g_cur[idx] = run;
        }
    }
}

__global__ void k_fill(const int* __restrict__ ei) {
    int e = blockIdx.x * blockDim.x + threadIdx.x;
    if (e < N_EDGES) {
        int d = load_dst(ei, e);
        int s = load_src(ei, e);
        if ((unsigned)d < (unsigned)N_NODES && (unsigned)s < (unsigned)N_NODES) {
            int pos = atomicAdd(&g_cur[d], 1);
            g_srcIdx[pos] = s;
        }
    }
}

// ---------------- aggregation: z[n] = h[n] + sum_{e: dst=n} h[src[e]] ---------
__global__ void k_agg(const float* __restrict__ hin) {
    int w = (blockIdx.x * blockDim.x + threadIdx.x) >> 5;
    int lane = threadIdx.x & 31;
    if (w >= N_NODES) return;
    const float4* hp = (const float4*)hin;
    float4 acc = __ldg(&hp[(size_t)w * 32 + lane]);
    int beg = g_off[w], end = g_off[w + 1];
    for (int e = beg; e < end; e++) {
        int s = __ldg(&g_srcIdx[e]);
        float4 v = __ldg(&hp[(size_t)s * 32 + lane]);
        acc.x += v.x; acc.y += v.y; acc.z += v.z; acc.w += v.w;
    }
    ((float4*)g_z)[(size_t)w * 32 + lane] = acc;
}

// ---------------- fused 2-layer MLP (tf32 mma.sync) ---------------------------
__device__ __forceinline__ uint32_t f2tf(float x) {
    uint32_t r;
    asm("cvt.rna.tf32.f32 %0, %1;" : "=r"(r) : "f"(x));
    return r;
}

__device__ __forceinline__ void mma8(float* c, const uint32_t* a, uint32_t b0, uint32_t b1) {
    asm volatile(
        "mma.sync.aligned.m16n8k8.row.col.f32.tf32.tf32.f32 "
        "{%0,%1,%2,%3},{%4,%5,%6,%7},{%8,%9},{%0,%1,%2,%3};"
        : "+f"(c[0]), "+f"(c[1]), "+f"(c[2]), "+f"(c[3])
        : "r"(a[0]), "r"(a[1]), "r"(a[2]), "r"(a[3]), "r"(b0), "r"(b1));
}

__device__ __forceinline__ void gemm_tile(float acc[2][8][4],
                                          const uint32_t* __restrict__ sA,
                                          const uint32_t* __restrict__ sW,
                                          int wm, int wn, int g, int t) {
#pragma unroll
    for (int ks = 0; ks < 16; ks++) {
        int k0 = ks * 8 + t;
        uint32_t a[2][4];
#pragma unroll
        for (int mt = 0; mt < 2; mt++) {
            int r0 = wm * 32 + mt * 16 + g;
            a[mt][0] = sA[r0 * SA_STRIDE + k0];
            a[mt][1] = sA[(r0 + 8) * SA_STRIDE + k0];
            a[mt][2] = sA[r0 * SA_STRIDE + k0 + 4];
            a[mt][3] = sA[(r0 + 8) * SA_STRIDE + k0 + 4];
        }
#pragma unroll
        for (int nt = 0; nt < 8; nt++) {
            int cn = wn * 64 + nt * 8 + g;
            uint32_t b0 = sW[k0 * SA_STRIDE + cn];
            uint32_t b1 = sW[(k0 + 4) * SA_STRIDE + cn];
            mma8(acc[0][nt], a[0], b0, b1);
            mma8(acc[1][nt], a[1], b0, b1);
        }
    }
}

__device__ __forceinline__ float elu(float v) {
    return v > 0.f ? v : expm1f(v);
}

__global__ void __launch_bounds__(256, 1)
k_mlp(const float* __restrict__ zin,
      const float* __restrict__ W1, const float* __restrict__ b1,
      const float* __restrict__ W2, const float* __restrict__ b2,
      float* __restrict__ hout) {
    extern __shared__ uint32_t sm[];
    uint32_t* sA = sm;                       // [128][SA_STRIDE] activations (tf32)
    uint32_t* sW = sm + 128 * SA_STRIDE;     // [128][SA_STRIDE] weights (tf32)
    int tid = threadIdx.x;
    int rowBase = blockIdx.x * 128;

    // stage z tile (rows) and W1 into smem as tf32
    for (int idx = tid; idx < 128 * 128; idx += 256) {
        int r = idx >> 7, k = idx & 127;
        int row = rowBase + r;
        float v = (row < N_NODES) ? zin[(size_t)row * 128 + k] : 0.f;
        sA[r * SA_STRIDE + k] = f2tf(v);
    }
    for (int idx = tid; idx < 128 * 128; idx += 256) {
        int k = idx >> 7, n = idx & 127;
        sW[k * SA_STRIDE + n] = f2tf(W1[idx]);
    }
    __syncthreads();

    int lane = tid & 31, warp = tid >> 5;
    int g = lane >> 2, t = lane & 3;
    int wm = warp & 3, wn = warp >> 2;

    float acc[2][8][4];
    // ---- phase 1: t = ELU(z @ W1 + b1) ----
#pragma unroll
    for (int mt = 0; mt < 2; mt++)
#pragma unroll
        for (int nt = 0; nt < 8; nt++) {
            int c0 = wn * 64 + nt * 8 + 2 * t;
            float v0 = __ldg(&b1[c0]), v1 = __ldg(&b1[c0 + 1]);
            acc[mt][nt][0] = v0; acc[mt][nt][1] = v1;
            acc[mt][nt][2] = v0; acc[mt][nt][3] = v1;
        }
    gemm_tile(acc, sA, sW, wm, wn, g, t);
#pragma unroll
    for (int mt = 0; mt < 2; mt++)
#pragma unroll
        for (int nt = 0; nt < 8; nt++)
#pragma unroll
            for (int i = 0; i < 4; i++)
                acc[mt][nt][i] = elu(acc[mt][nt][i]);

    __syncthreads();   // all reads of sA/sW for phase 1 complete

    // store t back into sA ([row][col=k2]) as tf32; reload sW with W2
#pragma unroll
    for (int mt = 0; mt < 2; mt++)
#pragma unroll
        for (int nt = 0; nt < 8; nt++) {
            int r0 = wm * 32 + mt * 16 + g;
            int c0 = wn * 64 + nt * 8 + 2 * t;
            sA[r0 * SA_STRIDE + c0]       = f2tf(acc[mt][nt][0]);
            sA[r0 * SA_STRIDE + c0 + 1]   = f2tf(acc[mt][nt][1]);
            sA[(r0 + 8) * SA_STRIDE + c0]     = f2tf(acc[mt][nt][2]);
            sA[(r0 + 8) * SA_STRIDE + c0 + 1] = f2tf(acc[mt][nt][3]);
        }
    for (int idx = tid; idx < 128 * 128; idx += 256) {
        int k = idx >> 7, n = idx & 127;
        sW[k * SA_STRIDE + n] = f2tf(W2[idx]);
    }
    __syncthreads();

    // ---- phase 2: h = ELU(t @ W2 + b2) ----
#pragma unroll
    for (int mt = 0; mt < 2; mt++)
#pragma unroll
        for (int nt = 0; nt < 8; nt++) {
            int c0 = wn * 64 + nt * 8 + 2 * t;
            float v0 = __ldg(&b2[c0]), v1 = __ldg(&b2[c0 + 1]);
            acc[mt][nt][0] = v0; acc[mt][nt][1] = v1;
            acc[mt][nt][2] = v0; acc[mt][nt][3] = v1;
        }
    gemm_tile(acc, sA, sW, wm, wn, g, t);

#pragma unroll
    for (int mt = 0; mt < 2; mt++)
#pragma unroll
        for (int nt = 0; nt < 8; nt++) {
            int r0 = rowBase + wm * 32 + mt * 16 + g;
            int c0 = wn * 64 + nt * 8 + 2 * t;
            if (r0 < N_NODES) {
                float2 v = make_float2(elu(acc[mt][nt][0]), elu(acc[mt][nt][1]));
                *(float2*)&hout[(size_t)r0 * 128 + c0] = v;
            }
            if (r0 + 8 < N_NODES) {
                float2 v = make_float2(elu(acc[mt][nt][2]), elu(acc[mt][nt][3]));
                *(float2*)&hout[(size_t)(r0 + 8) * 128 + c0] = v;
            }
        }
}

// ---------------- final FC: out = h @ fcW + fcb  (128 -> 10) ------------------
__global__ void k_fc(const float* __restrict__ h, const float* __restrict__ fcW,
                     const float* __restrict__ fcb, float* __restrict__ out) {
    __shared__ float sW[128 * 10];
    __shared__ float sb[16];
    int tid = threadIdx.x;
    for (int i = tid; i < 1280; i += 256) sW[i] = fcW[i];
    if (tid < 10) sb[tid] = fcb[tid];
    __syncthreads();
    int w = (blockIdx.x * 256 + tid) >> 5;
    int lane = tid & 31;
    if (w >= N_NODES) return;
    float4 hv = __ldg(&((const float4*)h)[(size_t)w * 32 + lane]);
    int k = lane * 4;
    float p[10];
#pragma unroll
    for (int j = 0; j < 10; j++)
        p[j] = hv.x * sW[k * 10 + j] + hv.y * sW[(k + 1) * 10 + j] +
               hv.z * sW[(k + 2) * 10 + j] + hv.w * sW[(k + 3) * 10 + j];
#pragma unroll
    for (int j = 0; j < 10; j++)
#pragma unroll
        for (int o = 16; o > 0; o >>= 1)
            p[j] += __shfl_xor_sync(0xffffffffu, p[j], o);
    if (lane == 0) {
#pragma unroll
        for (int j = 0; j < 10; j++)
            out[(size_t)w * 10 + j] = p[j] + sb[j];
    }
}

// ---------------- launch ------------------------------------------------------
extern "C" void kernel_launch(void* const* d_in, const int* in_sizes, int n_in,
                              void* d_out, int out_size) {
    const float* x   = (const float*)d_in[0];
    const int*   ei  = (const int*)d_in[1];   // int32 OR int64; probed on device
    // d_in[2]: edge_weight (unused by the reference)
    const float* Wa  = (const float*)d_in[3];
    const float* ba  = (const float*)d_in[4];
    const float* Wb  = (const float*)d_in[5];
    const float* bb  = (const float*)d_in[6];
    const float* fcW = (const float*)d_in[7];
    const float* fcb = (const float*)d_in[8];
    float*       out = (float*)d_out;

    const size_t MLP_SMEM = (size_t)2 * 128 * SA_STRIDE * sizeof(uint32_t);
    cudaFuncSetAttribute(k_mlp, cudaFuncAttributeMaxDynamicSharedMemorySize, (int)MLP_SMEM);

    void *pz = nullptr, *ph = nullptr;
    cudaGetSymbolAddress(&pz, g_z);
    cudaGetSymbolAddress(&ph, g_h);
    const float* zptr = (const float*)pz;
    float*       hptr = (float*)ph;

    // CSR build (recomputed deterministically each call)
    k_detect<<<1, 256>>>((const unsigned int*)ei);
    k_zero<<<(N_NODES + 1 + 255) / 256, 256>>>();
    k_count<<<(N_EDGES + 255) / 256, 256>>>(ei);
    k_scan<<<1, 1024>>>();
    k_fill<<<(N_EDGES + 255) / 256, 256>>>(ei);

    const int aggBlocks = (N_NODES * 32 + 255) / 256;
    const int mlpBlocks = (N_NODES + 127) / 128;
    for (int l = 0; l < 3; l++) {
        const float* hin = (l == 0) ? x : (const float*)hptr;
        k_agg<<<aggBlocks, 256>>>(hin);
        k_mlp<<<mlpBlocks, 256, MLP_SMEM>>>(zptr,
                                            Wa + (size_t)l * 128 * 128, ba + (size_t)l * 128,
                                            Wb + (size_t)l * 128 * 128, bb + (size_t)l * 128,
                                            hptr);
    }
    k_fc<<<(N_NODES * 32 + 255) / 256, 256>>>(hptr, fcW, fcb, out);
}

// round 3
// speedup vs baseline: 1.1699x; 1.1699x over previous
#include <cuda_runtime.h>
#include <cstdint>

#define N_NODES 100000
#define N_EDGES 1600000
#define HID 128
#define SA_STRIDE 132
#define SCAN_N (N_NODES + 1)
#define SCAN_NB ((SCAN_N + 255) / 256)   // 391

// ---------------- scratch (device globals: no allocation allowed) -------------
__device__ float g_z[(size_t)N_NODES * HID];   // aggregated features
__device__ float g_h[(size_t)N_NODES * HID];   // layer output features
__device__ int   g_off[N_NODES + 1];           // CSR offsets (by dst)
__device__ int   g_cur[N_NODES];               // fill cursors
__device__ int   g_srcIdx[N_EDGES];            // CSR column (src node) indices
__device__ int   g_bsum[SCAN_NB];              // per-block sums for scan
__device__ int   g_is64;                       // edge_index stored as int64?

// ---------------- dtype probe: int64 vs int32 edge_index ----------------------
__global__ void k_detect(const unsigned int* __restrict__ p) {
    __shared__ unsigned int sOr;
    if (threadIdx.x == 0) sOr = 0u;
    __syncthreads();
    unsigned int v = 0u;
    // If int64: words at odd positions (high halves) are all 0 (ids >= 0, < 2^31).
    for (int i = threadIdx.x; i < 4096; i += 256) v |= p[2 * i + 1];
    atomicOr(&sOr, v);
    __syncthreads();
    if (threadIdx.x == 0) g_is64 = (sOr == 0u) ? 1 : 0;
}

__device__ __forceinline__ int load_src(const int* ei, int e) {
    return g_is64 ? ei[2 * e] : ei[e];
}
__device__ __forceinline__ int load_dst(const int* ei, int e) {
    return g_is64 ? ei[2 * (N_EDGES + e)] : ei[N_EDGES + e];
}

// ---------------- CSR build ---------------------------------------------------
__global__ void k_zero() {
    int i = blockIdx.x * blockDim.x + threadIdx.x;
    if (i <= N_NODES) g_off[i] = 0;
}

__global__ void k_count(const int* __restrict__ ei) {
    int e = blockIdx.x * blockDim.x + threadIdx.x;
    if (e < N_EDGES) {
        int d = load_dst(ei, e);
        if ((unsigned)d < (unsigned)N_NODES) atomicAdd(&g_off[d + 1], 1);
    }
}

// ---- hierarchical inclusive scan of g_off[0..N_NODES] ----
// stage 1: per-block (256 elems) sums
__global__ void k_scan1() {
    __shared__ int sred[8];
    int idx = blockIdx.x * 256 + threadIdx.x;
    int v = (idx < SCAN_N) ? g_off[idx] : 0;
    int lane = threadIdx.x & 31, warp = threadIdx.x >> 5;
#pragma unroll
    for (int o = 16; o > 0; o >>= 1) v += __shfl_xor_sync(0xffffffffu, v, o);
    if (lane == 0) sred[warp] = v;
    __syncthreads();
    if (threadIdx.x == 0) {
        int s = 0;
#pragma unroll
        for (int w = 0; w < 8; w++) s += sred[w];
        g_bsum[blockIdx.x] = s;
    }
}

// stage 2: inclusive scan of the 391 block sums (single block)
__global__ void k_scan2() {
    __shared__ int sv[512];
    int tid = threadIdx.x;
    sv[tid] = (tid < SCAN_NB) ? g_bsum[tid] : 0;
    __syncthreads();
#pragma unroll
    for (int st = 1; st < 512; st <<= 1) {
        int v = (tid >= st) ? sv[tid - st] : 0;
        __syncthreads();
        sv[tid] += v;
        __syncthreads();
    }
    if (tid < SCAN_NB) g_bsum[tid] = sv[tid];
}

// stage 3: per-block inclusive scan + exclusive block offset; write g_off/g_cur
__global__ void k_scan3() {
    __shared__ int sv[256];
    int tid = threadIdx.x;
    int idx = blockIdx.x * 256 + tid;
    int v = (idx < SCAN_N) ? g_off[idx] : 0;
    sv[tid] = v;
    __syncthreads();
#pragma unroll
    for (int st = 1; st < 256; st <<= 1) {
        int t = (tid >= st) ? sv[tid - st] : 0;
        __syncthreads();
        sv[tid] += t;
        __syncthreads();
    }
    int off = (blockIdx.x > 0) ? g_bsum[blockIdx.x - 1] : 0;
    int res = sv[tid] + off;
    if (idx < SCAN_N) {
        g_off[idx] = res;                   // start offset of node idx
        if (idx < N_NODES) g_cur[idx] = res;
    }
}

__global__ void k_fill(const int* __restrict__ ei) {
    int e = blockIdx.x * blockDim.x + threadIdx.x;
    if (e < N_EDGES) {
        int d = load_dst(ei, e);
        int s = load_src(ei, e);
        if ((unsigned)d < (unsigned)N_NODES && (unsigned)s < (unsigned)N_NODES) {
            int pos = atomicAdd(&g_cur[d], 1);
            g_srcIdx[pos] = s;
        }
    }
}

// ---------------- aggregation: z[n] = h[n] + sum_{e: dst=n} h[src[e]] ---------
__global__ void k_agg(const float* __restrict__ hin) {
    int w = (blockIdx.x * blockDim.x + threadIdx.x) >> 5;
    int lane = threadIdx.x & 31;
    if (w >= N_NODES) return;
    const float4* hp = (const float4*)hin;
    float4 acc = __ldg(&hp[(size_t)w * 32 + lane]);
    int beg = g_off[w], end = g_off[w + 1];
    int e = beg;
    // 4-way unrolled: batch independent L2 loads for MLP >= 4
    for (; e + 4 <= end; e += 4) {
        int s0 = __ldg(&g_srcIdx[e]);
        int s1 = __ldg(&g_srcIdx[e + 1]);
        int s2 = __ldg(&g_srcIdx[e + 2]);
        int s3 = __ldg(&g_srcIdx[e + 3]);
        float4 v0 = __ldg(&hp[(size_t)s0 * 32 + lane]);
        float4 v1 = __ldg(&hp[(size_t)s1 * 32 + lane]);
        float4 v2 = __ldg(&hp[(size_t)s2 * 32 + lane]);
        float4 v3 = __ldg(&hp[(size_t)s3 * 32 + lane]);
        acc.x += v0.x + v1.x + v2.x + v3.x;
        acc.y += v0.y + v1.y + v2.y + v3.y;
        acc.z += v0.z + v1.z + v2.z + v3.z;
        acc.w += v0.w + v1.w + v2.w + v3.w;
    }
    for (; e < end; e++) {
        int s = __ldg(&g_srcIdx[e]);
        float4 v = __ldg(&hp[(size_t)s * 32 + lane]);
        acc.x += v.x; acc.y += v.y; acc.z += v.z; acc.w += v.w;
    }
    ((float4*)g_z)[(size_t)w * 32 + lane] = acc;
}

// ---------------- fused 2-layer MLP (tf32 mma.sync) ---------------------------
__device__ __forceinline__ uint32_t f2tf(float x) {
    uint32_t r;
    asm("cvt.rna.tf32.f32 %0, %1;" : "=r"(r) : "f"(x));
    return r;
}

__device__ __forceinline__ void mma8(float* c, const uint32_t* a, uint32_t b0, uint32_t b1) {
    asm volatile(
        "mma.sync.aligned.m16n8k8.row.col.f32.tf32.tf32.f32 "
        "{%0,%1,%2,%3},{%4,%5,%6,%7},{%8,%9},{%0,%1,%2,%3};"
        : "+f"(c[0]), "+f"(c[1]), "+f"(c[2]), "+f"(c[3])
        : "r"(a[0]), "r"(a[1]), "r"(a[2]), "r"(a[3]), "r"(b0), "r"(b1));
}

__device__ __forceinline__ void gemm_tile(float acc[2][8][4],
                                          const uint32_t* __restrict__ sA,
                                          const uint32_t* __restrict__ sW,
                                          int wm, int wn, int g, int t) {
#pragma unroll
    for (int ks = 0; ks < 16; ks++) {
        int k0 = ks * 8 + t;
        uint32_t a[2][4];
#pragma unroll
        for (int mt = 0; mt < 2; mt++) {
            int r0 = wm * 32 + mt * 16 + g;
            a[mt][0] = sA[r0 * SA_STRIDE + k0];
            a[mt][1] = sA[(r0 + 8) * SA_STRIDE + k0];
            a[mt][2] = sA[r0 * SA_STRIDE + k0 + 4];
            a[mt][3] = sA[(r0 + 8) * SA_STRIDE + k0 + 4];
        }
#pragma unroll
        for (int nt = 0; nt < 8; nt++) {
            int cn = wn * 64 + nt * 8 + g;
            uint32_t b0 = sW[k0 * SA_STRIDE + cn];
            uint32_t b1 = sW[(k0 + 4) * SA_STRIDE + cn];
            mma8(acc[0][nt], a[0], b0, b1);
            mma8(acc[1][nt], a[1], b0, b1);
        }
    }
}

__device__ __forceinline__ float elu(float v) {
    return v > 0.f ? v : expm1f(v);
}

__global__ void __launch_bounds__(256, 1)
k_mlp(const float* __restrict__ zin,
      const float* __restrict__ W1, const float* __restrict__ b1,
      const float* __restrict__ W2, const float* __restrict__ b2,
      float* __restrict__ hout) {
    extern __shared__ uint32_t sm[];
    uint32_t* sA = sm;                       // [128][SA_STRIDE] activations (tf32)
    uint32_t* sW = sm + 128 * SA_STRIDE;     // [128][SA_STRIDE] weights (tf32)
    int tid = threadIdx.x;
    int rowBase = blockIdx.x * 128;

    // stage z tile (rows) and W1 into smem as tf32
    for (int idx = tid; idx < 128 * 128; idx += 256) {
        int r = idx >> 7, k = idx & 127;
        int row = rowBase + r;
        float v = (row < N_NODES) ? zin[(size_t)row * 128 + k] : 0.f;
        sA[r * SA_STRIDE + k] = f2tf(v);
    }
    for (int idx = tid; idx < 128 * 128; idx += 256) {
        int k = idx >> 7, n = idx & 127;
        sW[k * SA_STRIDE + n] = f2tf(W1[idx]);
    }
    __syncthreads();

    int lane = tid & 31, warp = tid >> 5;
    int g = lane >> 2, t = lane & 3;
    int wm = warp & 3, wn = warp >> 2;

    float acc[2][8][4];
    // ---- phase 1: t = ELU(z @ W1 + b1) ----
#pragma unroll
    for (int mt = 0; mt < 2; mt++)
#pragma unroll
        for (int nt = 0; nt < 8; nt++) {
            int c0 = wn * 64 + nt * 8 + 2 * t;
            float v0 = __ldg(&b1[c0]), v1 = __ldg(&b1[c0 + 1]);
            acc[mt][nt][0] = v0; acc[mt][nt][1] = v1;
            acc[mt][nt][2] = v0; acc[mt][nt][3] = v1;
        }
    gemm_tile(acc, sA, sW, wm, wn, g, t);
#pragma unroll
    for (int mt = 0; mt < 2; mt++)
#pragma unroll
        for (int nt = 0; nt < 8; nt++)
#pragma unroll
            for (int i = 0; i < 4; i++)
                acc[mt][nt][i] = elu(acc[mt][nt][i]);

    __syncthreads();   // all reads of sA/sW for phase 1 complete

    // store t back into sA ([row][col=k2]) as tf32; reload sW with W2
#pragma unroll
    for (int mt = 0; mt < 2; mt++)
#pragma unroll
        for (int nt = 0; nt < 8; nt++) {
            int r0 = wm * 32 + mt * 16 + g;
            int c0 = wn * 64 + nt * 8 + 2 * t;
            sA[r0 * SA_STRIDE + c0]       = f2tf(acc[mt][nt][0]);
            sA[r0 * SA_STRIDE + c0 + 1]   = f2tf(acc[mt][nt][1]);
            sA[(r0 + 8) * SA_STRIDE + c0]     = f2tf(acc[mt][nt][2]);
            sA[(r0 + 8) * SA_STRIDE + c0 + 1] = f2tf(acc[mt][nt][3]);
        }
    for (int idx = tid; idx < 128 * 128; idx += 256) {
        int k = idx >> 7, n = idx & 127;
        sW[k * SA_STRIDE + n] = f2tf(W2[idx]);
    }
    __syncthreads();

    // ---- phase 2: h = ELU(t @ W2 + b2) ----
#pragma unroll
    for (int mt = 0; mt < 2; mt++)
#pragma unroll
        for (int nt = 0; nt < 8; nt++) {
            int c0 = wn * 64 + nt * 8 + 2 * t;
            float v0 = __ldg(&b2[c0]), v1 = __ldg(&b2[c0 + 1]);
            acc[mt][nt][0] = v0; acc[mt][nt][1] = v1;
            acc[mt][nt][2] = v0; acc[mt][nt][3] = v1;
        }
    gemm_tile(acc, sA, sW, wm, wn, g, t);

#pragma unroll
    for (int mt = 0; mt < 2; mt++)
#pragma unroll
        for (int nt = 0; nt < 8; nt++) {
            int r0 = rowBase + wm * 32 + mt * 16 + g;
            int c0 = wn * 64 + nt * 8 + 2 * t;
            if (r0 < N_NODES) {
                float2 v = make_float2(elu(acc[mt][nt][0]), elu(acc[mt][nt][1]));
                *(float2*)&hout[(size_t)r0 * 128 + c0] = v;
            }
            if (r0 + 8 < N_NODES) {
                float2 v = make_float2(elu(acc[mt][nt][2]), elu(acc[mt][nt][3]));
                *(float2*)&hout[(size_t)(r0 + 8) * 128 + c0] = v;
            }
        }
}

// ---------------- final FC: out = h @ fcW + fcb  (128 -> 10) ------------------
__global__ void k_fc(const float* __restrict__ h, const float* __restrict__ fcW,
                     const float* __restrict__ fcb, float* __restrict__ out) {
    __shared__ float sW[128 * 10];
    __shared__ float sb[16];
    int tid = threadIdx.x;
    for (int i = tid; i < 1280; i += 256) sW[i] = fcW[i];
    if (tid < 10) sb[tid] = fcb[tid];
    __syncthreads();
    int w = (blockIdx.x * 256 + tid) >> 5;
    int lane = tid & 31;
    if (w >= N_NODES) return;
    float4 hv = __ldg(&((const float4*)h)[(size_t)w * 32 + lane]);
    int k = lane * 4;
    float p[10];
#pragma unroll
    for (int j = 0; j < 10; j++)
        p[j] = hv.x * sW[k * 10 + j] + hv.y * sW[(k + 1) * 10 + j] +
               hv.z * sW[(k + 2) * 10 + j] + hv.w * sW[(k + 3) * 10 + j];
#pragma unroll
    for (int j = 0; j < 10; j++)
#pragma unroll
        for (int o = 16; o > 0; o >>= 1)
            p[j] += __shfl_xor_sync(0xffffffffu, p[j], o);
    if (lane == 0) {
#pragma unroll
        for (int j = 0; j < 10; j++)
            out[(size_t)w * 10 + j] = p[j] + sb[j];
    }
}

// ---------------- launch ------------------------------------------------------
extern "C" void kernel_launch(void* const* d_in, const int* in_sizes, int n_in,
                              void* d_out, int out_size) {
    const float* x   = (const float*)d_in[0];
    const int*   ei  = (const int*)d_in[1];   // int32 OR int64; probed on device
    // d_in[2]: edge_weight (unused by the reference)
    const float* Wa  = (const float*)d_in[3];
    const float* ba  = (const float*)d_in[4];
    const float* Wb  = (const float*)d_in[5];
    const float* bb  = (const float*)d_in[6];
    const float* fcW = (const float*)d_in[7];
    const float* fcb = (const float*)d_in[8];
    float*       out = (float*)d_out;

    const size_t MLP_SMEM = (size_t)2 * 128 * SA_STRIDE * sizeof(uint32_t);
    cudaFuncSetAttribute(k_mlp, cudaFuncAttributeMaxDynamicSharedMemorySize, (int)MLP_SMEM);

    void *pz = nullptr, *ph = nullptr;
    cudaGetSymbolAddress(&pz, g_z);
    cudaGetSymbolAddress(&ph, g_h);
    const float* zptr = (const float*)pz;
    float*       hptr = (float*)ph;

    // CSR build (recomputed deterministically each call)
    k_detect<<<1, 256>>>((const unsigned int*)ei);
    k_zero<<<(N_NODES + 1 + 255) / 256, 256>>>();
    k_count<<<(N_EDGES + 255) / 256, 256>>>(ei);
    k_scan1<<<SCAN_NB, 256>>>();
    k_scan2<<<1, 512>>>();
    k_scan3<<<SCAN_NB, 256>>>();
    k_fill<<<(N_EDGES + 255) / 256, 256>>>(ei);

    const int aggBlocks = (N_NODES * 32 + 255) / 256;
    const int mlpBlocks = (N_NODES + 127) / 128;
    for (int l = 0; l < 3; l++) {
        const float* hin = (l == 0) ? x : (const float*)hptr;
        k_agg<<<aggBlocks, 256>>>(hin);
        k_mlp<<<mlpBlocks, 256, MLP_SMEM>>>(zptr,
                                            Wa + (size_t)l * 128 * 128, ba + (size_t)l * 128,
                                            Wb + (size_t)l * 128 * 128, bb + (size_t)l * 128,
                                            hptr);
    }
    k_fc<<<(N_NODES * 32 + 255) / 256, 256>>>(hptr, fcW, fcb, out);
}

// round 4
// speedup vs baseline: 2.2152x; 1.8934x over previous
#include <cuda_runtime.h>
#include <cuda_fp16.h>
#include <cstdint>

#define N_NODES 100000
#define N_EDGES 1600000
#define HID 128
#define SAH 136                          // fp16 smem row stride (halves)
#define SCAN_N (N_NODES + 1)
#define SCAN_NB ((SCAN_N + 255) / 256)   // 391

// ---------------- scratch (device globals: no allocation allowed) -------------
__device__ float   g_z[(size_t)N_NODES * HID];     // aggregated features (fp32)
__device__ __half  g_hh[(size_t)N_NODES * HID];    // node features (fp16)
__device__ int     g_off[N_NODES + 1];
__device__ int     g_cur[N_NODES];
__device__ int     g_srcIdx[N_EDGES];
__device__ int     g_bsum[SCAN_NB];
__device__ int     g_is64;

// ---------------- dtype probe: int64 vs int32 edge_index ----------------------
__global__ void k_detect(const unsigned int* __restrict__ p) {
    __shared__ unsigned int sOr;
    if (threadIdx.x == 0) sOr = 0u;
    __syncthreads();
    unsigned int v = 0u;
    for (int i = threadIdx.x; i < 4096; i += 256) v |= p[2 * i + 1];
    atomicOr(&sOr, v);
    __syncthreads();
    if (threadIdx.x == 0) g_is64 = (sOr == 0u) ? 1 : 0;
}

__device__ __forceinline__ int load_src(const int* ei, int e) {
    return g_is64 ? ei[2 * e] : ei[e];
}
__device__ __forceinline__ int load_dst(const int* ei, int e) {
    return g_is64 ? ei[2 * (N_EDGES + e)] : ei[N_EDGES + e];
}

// ---------------- x (fp32) -> g_hh (fp16) --------------------------------------
__global__ void k_x2h(const float* __restrict__ x) {
    int i = blockIdx.x * blockDim.x + threadIdx.x;          // half2 index
    const int n2 = N_NODES * HID / 2;
    if (i < n2) {
        float2 v = ((const float2*)x)[i];
        ((__half2*)g_hh)[i] = __float22half2_rn(v);
    }
}

// ---------------- CSR build ---------------------------------------------------
__global__ void k_zero() {
    int i = blockIdx.x * blockDim.x + threadIdx.x;
    if (i <= N_NODES) g_off[i] = 0;
}

__global__ void k_count(const int* __restrict__ ei) {
    int e = blockIdx.x * blockDim.x + threadIdx.x;
    if (e < N_EDGES) {
        int d = load_dst(ei, e);
        if ((unsigned)d < (unsigned)N_NODES) atomicAdd(&g_off[d + 1], 1);
    }
}

__global__ void k_scan1() {
    __shared__ int sred[8];
    int idx = blockIdx.x * 256 + threadIdx.x;
    int v = (idx < SCAN_N) ? g_off[idx] : 0;
    int lane = threadIdx.x & 31, warp = threadIdx.x >> 5;
#pragma unroll
    for (int o = 16; o > 0; o >>= 1) v += __shfl_xor_sync(0xffffffffu, v, o);
    if (lane == 0) sred[warp] = v;
    __syncthreads();
    if (threadIdx.x == 0) {
        int s = 0;
#pragma unroll
        for (int w = 0; w < 8; w++) s += sred[w];
        g_bsum[blockIdx.x] = s;
    }
}

__global__ void k_scan2() {
    __shared__ int sv[512];
    int tid = threadIdx.x;
    sv[tid] = (tid < SCAN_NB) ? g_bsum[tid] : 0;
    __syncthreads();
#pragma unroll
    for (int st = 1; st < 512; st <<= 1) {
        int v = (tid >= st) ? sv[tid - st] : 0;
        __syncthreads();
        sv[tid] += v;
        __syncthreads();
    }
    if (tid < SCAN_NB) g_bsum[tid] = sv[tid];
}

__global__ void k_scan3() {
    __shared__ int sv[256];
    int tid = threadIdx.x;
    int idx = blockIdx.x * 256 + tid;
    int v = (idx < SCAN_N) ? g_off[idx] : 0;
    sv[tid] = v;
    __syncthreads();
#pragma unroll
    for (int st = 1; st < 256; st <<= 1) {
        int t = (tid >= st) ? sv[tid - st] : 0;
        __syncthreads();
        sv[tid] += t;
        __syncthreads();
    }
    int off = (blockIdx.x > 0) ? g_bsum[blockIdx.x - 1] : 0;
    int res = sv[tid] + off;
    if (idx < SCAN_N) {
        g_off[idx] = res;
        if (idx < N_NODES) g_cur[idx] = res;
    }
}

__global__ void k_fill(const int* __restrict__ ei) {
    int e = blockIdx.x * blockDim.x + threadIdx.x;
    if (e < N_EDGES) {
        int d = load_dst(ei, e);
        int s = load_src(ei, e);
        if ((unsigned)d < (unsigned)N_NODES && (unsigned)s < (unsigned)N_NODES) {
            int pos = atomicAdd(&g_cur[d], 1);
            g_srcIdx[pos] = s;
        }
    }
}

// ---------------- aggregation: z[n] = h[n] + sum h[src]  (h fp16 -> z fp32) ----
__device__ __forceinline__ void add8(float* a, uint4 v) {
    float2 f0 = __half22float2(*(__half2*)&v.x);
    float2 f1 = __half22float2(*(((__half2*)&v.x) + 1));
    float2 f2 = __half22float2(*(__half2*)&v.z);
    float2 f3 = __half22float2(*(((__half2*)&v.z) + 1));
    a[0] += f0.x; a[1] += f0.y; a[2] += f1.x; a[3] += f1.y;
    a[4] += f2.x; a[5] += f2.y; a[6] += f3.x; a[7] += f3.y;
}

__global__ void k_agg() {
    // 16 lanes per node; each lane owns 8 consecutive channels (one uint4 of fp16)
    int node = (blockIdx.x * blockDim.x + threadIdx.x) >> 4;
    int sub = threadIdx.x & 15;
    if (node >= N_NODES) return;
    const uint4* hp = (const uint4*)g_hh;      // 16 uint4 per row
    float acc[8] = {0, 0, 0, 0, 0, 0, 0, 0};
    add8(acc, __ldg(&hp[(size_t)node * 16 + sub]));
    int beg = g_off[node], end = g_off[node + 1];
    int e = beg;
    for (; e + 4 <= end; e += 4) {
        int s0 = __ldg(&g_srcIdx[e]);
        int s1 = __ldg(&g_srcIdx[e + 1]);
        int s2 = __ldg(&g_srcIdx[e + 2]);
        int s3 = __ldg(&g_srcIdx[e + 3]);
        uint4 v0 = __ldg(&hp[(size_t)s0 * 16 + sub]);
        uint4 v1 = __ldg(&hp[(size_t)s1 * 16 + sub]);
        uint4 v2 = __ldg(&hp[(size_t)s2 * 16 + sub]);
        uint4 v3 = __ldg(&hp[(size_t)s3 * 16 + sub]);
        add8(acc, v0); add8(acc, v1); add8(acc, v2); add8(acc, v3);
    }
    for (; e < end; e++) {
        int s = __ldg(&g_srcIdx[e]);
        add8(acc, __ldg(&hp[(size_t)s * 16 + sub]));
    }
    float4* zp = (float4*)g_z;                  // 32 float4 per row
    zp[(size_t)node * 32 + sub * 2]     = make_float4(acc[0], acc[1], acc[2], acc[3]);
    zp[(size_t)node * 32 + sub * 2 + 1] = make_float4(acc[4], acc[5], acc[6], acc[7]);
}

// ---------------- fused 2-layer MLP (fp16 mma.m16n8k16 + ldmatrix) ------------
__device__ __forceinline__ uint32_t smem_u32(const void* p) {
    return (uint32_t)__cvta_generic_to_shared(p);
}

__device__ __forceinline__ void ldsm_x4(uint32_t& r0, uint32_t& r1, uint32_t& r2,
                                        uint32_t& r3, uint32_t addr) {
    asm volatile("ldmatrix.sync.aligned.m8n8.x4.shared.b16 {%0,%1,%2,%3}, [%4];"
                 : "=r"(r0), "=r"(r1), "=r"(r2), "=r"(r3) : "r"(addr));
}

__device__ __forceinline__ void ldsm_x4_t(uint32_t& r0, uint32_t& r1, uint32_t& r2,
                                          uint32_t& r3, uint32_t addr) {
    asm volatile("ldmatrix.sync.aligned.m8n8.x4.trans.shared.b16 {%0,%1,%2,%3}, [%4];"
                 : "=r"(r0), "=r"(r1), "=r"(r2), "=r"(r3) : "r"(addr));
}

__device__ __forceinline__ void mma16(float* c, const uint32_t* a, uint32_t b0, uint32_t b1) {
    asm volatile(
        "mma.sync.aligned.m16n8k16.row.col.f32.f16.f16.f32 "
        "{%0,%1,%2,%3},{%4,%5,%6,%7},{%8,%9},{%0,%1,%2,%3};"
        : "+f"(c[0]), "+f"(c[1]), "+f"(c[2]), "+f"(c[3])
        : "r"(a[0]), "r"(a[1]), "r"(a[2]), "r"(a[3]), "r"(b0), "r"(b1));
}

__device__ __forceinline__ float elu(float v) {
    return v > 0.f ? v : expm1f(v);
}

// GEMM over staged fp16 tiles: acc[2][8][4] += sA(128xK) @ sW(Kx128) warp tile 32x64
__device__ __forceinline__ void gemm_tile16(float acc[2][8][4],
                                            const __half* sA, const __half* sW,
                                            int wm, int wn, int lane) {
    int lr = lane & 15, sel = lane >> 4;      // A ldmatrix addressing
    int l7 = lane & 7, seg = lane >> 3;       // B ldmatrix.trans addressing
#pragma unroll
    for (int ks = 0; ks < 8; ks++) {
        int k0 = ks * 16;
        uint32_t a[2][4];
#pragma unroll
        for (int mt = 0; mt < 2; mt++) {
            int r0 = wm * 32 + mt * 16;
            uint32_t addr = smem_u32(&sA[(r0 + lr) * SAH + k0 + sel * 8]);
            ldsm_x4(a[mt][0], a[mt][1], a[mt][2], a[mt][3], addr);
        }
#pragma unroll
        for (int np = 0; np < 4; np++) {       // 4 n16 groups = 64 cols
            int c0 = wn * 64 + np * 16;
            int brow = k0 + (seg & 1) * 8 + l7;
            int bcol = c0 + (seg >> 1) * 8;
            uint32_t b0, b1, b2, b3;
            ldsm_x4_t(b0, b1, b2, b3, smem_u32(&sW[brow * SAH + bcol]));
            mma16(acc[0][np * 2],     a[0], b0, b1);
            mma16(acc[1][np * 2],     a[1], b0, b1);
            mma16(acc[0][np * 2 + 1], a[0], b2, b3);
            mma16(acc[1][np * 2 + 1], a[1], b2, b3);
        }
    }
}

__global__ void __launch_bounds__(256, 2)
k_mlp(const float* __restrict__ zin,
      const float* __restrict__ W1, const float* __restrict__ b1,
      const float* __restrict__ W2, const float* __restrict__ b2,
      __half* __restrict__ hout) {
    extern __shared__ __half sm[];
    __half* sA = sm;                 // [128][SAH]
    __half* sW = sm + 128 * SAH;     // [128][SAH]
    int tid = threadIdx.x;
    int rowBase = blockIdx.x * 128;

    // stage z tile and W1 (fp32 -> fp16), 2 cols per iteration
    for (int idx = tid; idx < 128 * 64; idx += 256) {
        int r = idx >> 6, k2 = (idx & 63) * 2;
        int row = rowBase + r;
        float2 v = (row < N_NODES) ? *(const float2*)&zin[(size_t)row * 128 + k2]
                                   : make_float2(0.f, 0.f);
        *(__half2*)&sA[r * SAH + k2] = __float22half2_rn(v);
    }
    for (int idx = tid; idx < 128 * 64; idx += 256) {
        int k = idx >> 6, n2 = (idx & 63) * 2;
        float2 v = *(const float2*)&W1[(size_t)k * 128 + n2];
        *(__half2*)&sW[k * SAH + n2] = __float22half2_rn(v);
    }
    __syncthreads();

    int lane = tid & 31, warp = tid >> 5;
    int g = lane >> 2, t = lane & 3;
    int wm = warp & 3, wn = warp >> 2;

    float acc[2][8][4];
    // ---- phase 1: t = ELU(z @ W1 + b1) ----
#pragma unroll
    for (int mt = 0; mt < 2; mt++)
#pragma unroll
        for (int nt = 0; nt < 8; nt++) {
            int c0 = wn * 64 + nt * 8 + 2 * t;
            float v0 = __ldg(&b1[c0]), v1 = __ldg(&b1[c0 + 1]);
            acc[mt][nt][0] = v0; acc[mt][nt][1] = v1;
            acc[mt][nt][2] = v0; acc[mt][nt][3] = v1;
        }
    gemm_tile16(acc, sA, sW, wm, wn, lane);

    __syncthreads();   // phase-1 reads complete before overwrite

    // ELU -> fp16 -> sA ; reload sW with W2
#pragma unroll
    for (int mt = 0; mt < 2; mt++)
#pragma unroll
        for (int nt = 0; nt < 8; nt++) {
            int r0 = wm * 32 + mt * 16 + g;
            int c0 = wn * 64 + nt * 8 + 2 * t;
            *(__half2*)&sA[r0 * SAH + c0] =
                __floats2half2_rn(elu(acc[mt][nt][0]), elu(acc[mt][nt][1]));
            *(__half2*)&sA[(r0 + 8) * SAH + c0] =
                __floats2half2_rn(elu(acc[mt][nt][2]), elu(acc[mt][nt][3]));
        }
    for (int idx = tid; idx < 128 * 64; idx += 256) {
        int k = idx >> 6, n2 = (idx & 63) * 2;
        float2 v = *(const float2*)&W2[(size_t)k * 128 + n2];
        *(__half2*)&sW[k * SAH + n2] = __float22half2_rn(v);
    }
    __syncthreads();

    // ---- phase 2: h = ELU(t @ W2 + b2) ----
#pragma unroll
    for (int mt = 0; mt < 2; mt++)
#pragma unroll
        for (int nt = 0; nt < 8; nt++) {
            int c0 = wn * 64 + nt * 8 + 2 * t;
            float v0 = __ldg(&b2[c0]), v1 = __ldg(&b2[c0 + 1]);
            acc[mt][nt][0] = v0; acc[mt][nt][1] = v1;
            acc[mt][nt][2] = v0; acc[mt][nt][3] = v1;
        }
    gemm_tile16(acc, sA, sW, wm, wn, lane);

#pragma unroll
    for (int mt = 0; mt < 2; mt++)
#pragma unroll
        for (int nt = 0; nt < 8; nt++) {
            int r0 = rowBase + wm * 32 + mt * 16 + g;
            int c0 = wn * 64 + nt * 8 + 2 * t;
            if (r0 < N_NODES)
                *(__half2*)&hout[(size_t)r0 * 128 + c0] =
                    __floats2half2_rn(elu(acc[mt][nt][0]), elu(acc[mt][nt][1]));
            if (r0 + 8 < N_NODES)
                *(__half2*)&hout[(size_t)(r0 + 8) * 128 + c0] =
                    __floats2half2_rn(elu(acc[mt][nt][2]), elu(acc[mt][nt][3]));
        }
}

// ---------------- final FC: out = h(fp16) @ fcW + fcb  (128 -> 10) ------------
__global__ void k_fc(const float* __restrict__ fcW,
                     const float* __restrict__ fcb, float* __restrict__ out) {
    __shared__ float sW[128 * 10];
    __shared__ float sb[16];
    int tid = threadIdx.x;
    for (int i = tid; i < 1280; i += 256) sW[i] = fcW[i];
    if (tid < 10) sb[tid] = fcb[tid];
    __syncthreads();
    int w = (blockIdx.x * 256 + tid) >> 5;
    int lane = tid & 31;
    if (w >= N_NODES) return;
    uint2 hv = __ldg(&((const uint2*)g_hh)[(size_t)w * 32 + lane]);
    float2 f0 = __half22float2(*(__half2*)&hv.x);
    float2 f1 = __half22float2(*(__half2*)&hv.y);
    int k = lane * 4;
    float p[10];
#pragma unroll
    for (int j = 0; j < 10; j++)
        p[j] = f0.x * sW[k * 10 + j] + f0.y * sW[(k + 1) * 10 + j] +
               f1.x * sW[(k + 2) * 10 + j] + f1.y * sW[(k + 3) * 10 + j];
#pragma unroll
    for (int j = 0; j < 10; j++)
#pragma unroll
        for (int o = 16; o > 0; o >>= 1)
            p[j] += __shfl_xor_sync(0xffffffffu, p[j], o);
    if (lane == 0) {
#pragma unroll
        for (int j = 0; j < 10; j++)
            out[(size_t)w * 10 + j] = p[j] + sb[j];
    }
}

// ---------------- launch ------------------------------------------------------
extern "C" void kernel_launch(void* const* d_in, const int* in_sizes, int n_in,
                              void* d_out, int out_size) {
    const float* x   = (const float*)d_in[0];
    const int*   ei  = (const int*)d_in[1];   // int32 OR int64; probed on device
    const float* Wa  = (const float*)d_in[3];
    const float* ba  = (const float*)d_in[4];
    const float* Wb  = (const float*)d_in[5];
    const float* bb  = (const float*)d_in[6];
    const float* fcW = (const float*)d_in[7];
    const float* fcb = (const float*)d_in[8];
    float*       out = (float*)d_out;

    const size_t MLP_SMEM = (size_t)2 * 128 * SAH * sizeof(__half);   // ~68 KB
    cudaFuncSetAttribute(k_mlp, cudaFuncAttributeMaxDynamicSharedMemorySize, (int)MLP_SMEM);

    void *pz = nullptr, *ph = nullptr;
    cudaGetSymbolAddress(&pz, g_z);
    cudaGetSymbolAddress(&ph, g_hh);
    const float* zptr = (const float*)pz;
    __half*      hptr = (__half*)ph;

    // CSR build + x conversion
    k_detect<<<1, 256>>>((const unsigned int*)ei);
    k_x2h<<<(N_NODES * HID / 2 + 255) / 256, 256>>>(x);
    k_zero<<<(N_NODES + 1 + 255) / 256, 256>>>();
    k_count<<<(N_EDGES + 255) / 256, 256>>>(ei);
    k_scan1<<<SCAN_NB, 256>>>();
    k_scan2<<<1, 512>>>();
    k_scan3<<<SCAN_NB, 256>>>();
    k_fill<<<(N_EDGES + 255) / 256, 256>>>(ei);

    const int aggBlocks = (N_NODES * 16 + 255) / 256;
    const int mlpBlocks = (N_NODES + 127) / 128;
    for (int l = 0; l < 3; l++) {
        k_agg<<<aggBlocks, 256>>>();
        k_mlp<<<mlpBlocks, 256, MLP_SMEM>>>(zptr,
                                            Wa + (size_t)l * 128 * 128, ba + (size_t)l * 128,
                                            Wb + (size_t)l * 128 * 128, bb + (size_t)l * 128,
                                            hptr);
    }
    k_fc<<<(N_NODES * 32 + 255) / 256, 256>>>(fcW, fcb, out);
}